// round 16
// baseline (speedup 1.0000x reference)
#include <cuda_runtime.h>
#include <cuda_fp16.h>
#include <cstdint>

#define NUM_HEADS   8
#define HIDDEN_DIM  64
#define N_REAL      30000
#define N_VIRT      2000
#define N_NODES     (N_REAL + N_VIRT)
#define N_EDGES     512000
#define VEC_PER_ROW 16                 // float4 (or uint2-of-half4) per node row
#define TB 256
#define NBLK 592                       // 4 blocks/SM on 148 SMs — one co-resident wave
#define GSTRIDE (NBLK * TB)
#define N_REP 4                        // h2 replicas to de-contend REDG
#define E_PER 4

// ---- device scratch (allocation-free) --------------------------------------
// Invariant: g_z is ZERO on entry (static zero-init at load; re-zeroed in
// phase 4 on every call).
struct __align__(16) Zeroed {
    int indeg[N_NODES];
    int vcnt;
    unsigned char needed[N_NODES];
};
__device__ Zeroed  g_z;
#define ZERO_CHUNKS  ((unsigned)((sizeof(Zeroed) + 15) / 16))

__device__ __half2 g_h0h[N_NODES * 32];            // f16 node features, 4 MB
__device__ float4  g_h1[N_NODES * VEC_PER_ROW];    // round-1 raw sums, 8 MB
__device__ float4  g_h2[N_REP][N_VIRT * VEC_PER_ROW]; // round-2 replicas, 2 MB
__device__ int     g_vpack[N_EDGES];               // packed (src | vdst<<16)
__device__ float   g_wv[N_VIRT];                   // winv of virtual nodes

// software global barrier state (monotonic generation; count resets itself)
__device__ unsigned g_bar_count;
__device__ unsigned g_bar_gen;

__device__ __forceinline__ void red_add_v4(float4* addr, float4 v) {
    asm volatile("red.global.add.v4.f32 [%0], {%1,%2,%3,%4};"
                 :: "l"(addr), "f"(v.x), "f"(v.y), "f"(v.z), "f"(v.w)
                 : "memory");
}
__device__ __forceinline__ float winv_of(int node) {
    float di = (float)g_z.indeg[node];
    return di > 0.f ? __frcp_rn(di) : 0.f;
}

// Grid-wide barrier for exactly NBLK co-resident blocks.
__device__ __forceinline__ void grid_barrier() {
    __syncthreads();
    if (threadIdx.x == 0) {
        unsigned gen = *(volatile unsigned*)&g_bar_gen;
        __threadfence();                       // make phase writes visible
        unsigned arrived = atomicAdd(&g_bar_count, 1u);
        if (arrived == NBLK - 1) {
            g_bar_count = 0;
            __threadfence();
            atomicExch(&g_bar_gen, gen + 1u);  // release
        } else {
            while (*(volatile unsigned*)&g_bar_gen == gen) { __nanosleep(64); }
        }
        __threadfence();                       // acquire
    }
    __syncthreads();
}

// ---------------------------------------------------------------------------
// One persistent kernel; phases separated by grid barriers.
__global__ void __launch_bounds__(TB) k_all(
        const float4* __restrict__ features,
        const float4* __restrict__ virtue_emb,
        const int* __restrict__ cnodes,
        const int* __restrict__ src,
        const int* __restrict__ dst,
        const int* __restrict__ vm_idx,
        float4* __restrict__ out) {
    const int g = blockIdx.x * TB + threadIdx.x;

    // ---------------- Phase 1: prep -----------------------------------------
    // indeg histogram + virtual-pair compaction (one pass over edges)
    for (int e = g; e < N_EDGES; e += GSTRIDE) {
        int dd = dst[e];
        atomicAdd(&g_z.indeg[dd], 1);
        if (dd >= N_REAL) {
            int s = src[e];
            int pos = atomicAdd(&g_z.vcnt, 1);
            g_vpack[pos] = s | ((dd - N_REAL) << 16);
            g_z.needed[s] = 1;                 // benign race
        }
    }
    // build f16 h0
    for (int t = g; t < N_NODES * VEC_PER_ROW; t += GSTRIDE) {
        int v = t >> 4;
        int c = t & 15;
        float4 x;
        if (v < N_REAL) {
            int w = cnodes[v];
            x = features[(size_t)w * VEC_PER_ROW + c];
        } else {
            x = virtue_emb[(size_t)(v - N_REAL) * VEC_PER_ROW + c];
        }
        g_h0h[t * 2]     = __floats2half2_rn(x.x, x.y);
        g_h0h[t * 2 + 1] = __floats2half2_rn(x.z, x.w);
    }
    // zero h1 and h2
    for (int t = g; t < N_NODES * VEC_PER_ROW; t += GSTRIDE)
        g_h1[t] = make_float4(0.f, 0.f, 0.f, 0.f);
    for (int t = g; t < N_REP * N_VIRT * VEC_PER_ROW; t += GSTRIDE)
        ((float4*)g_h2)[t] = make_float4(0.f, 0.f, 0.f, 0.f);

    grid_barrier();

    // ---------------- Phase 2: round 1 --------------------------------------
    // h1raw[d] += h0f16[s] for needed dst; 16 lanes/edge, 4 edges per item.
    {
        const uint2* h0 = reinterpret_cast<const uint2*>(g_h0h);
        const int total = (N_EDGES / E_PER) * VEC_PER_ROW;
        for (int t = g; t < total; t += GSTRIDE) {
            int c  = t & 15;
            int e0 = (t >> 4) * E_PER;

            int s[E_PER], d[E_PER];
#pragma unroll
            for (int j = 0; j < E_PER; j++) { s[j] = src[e0 + j]; d[j] = dst[e0 + j]; }
            unsigned char f[E_PER];
#pragma unroll
            for (int j = 0; j < E_PER; j++) f[j] = g_z.needed[d[j]];

            uint2 q[E_PER];
#pragma unroll
            for (int j = 0; j < E_PER; j++)
                if (f[j]) q[j] = h0[s[j] * VEC_PER_ROW + c];
#pragma unroll
            for (int j = 0; j < E_PER; j++) {
                if (!f[j]) continue;
                __half2 a  = *reinterpret_cast<__half2*>(&q[j].x);
                __half2 bb = *reinterpret_cast<__half2*>(&q[j].y);
                float2 fa = __half22float2(a);
                float2 fb = __half22float2(bb);
                red_add_v4(&g_h1[d[j] * VEC_PER_ROW + c],
                           make_float4(fa.x, fa.y, fb.x, fb.y));
            }
        }
    }

    grid_barrier();

    // ---------------- Phase 3: round 2 + g_wv -------------------------------
    {
        int nv = g_z.vcnt;
        int total = nv * VEC_PER_ROW;
        int rep = (threadIdx.x >> 5) & (N_REP - 1);
        for (int t = g; t < total; t += GSTRIDE) {
            int e = t >> 4;
            int c = t & 15;
            int pk = g_vpack[e];
            int s = pk & 0xFFFF;
            int r = pk >> 16;
            float w = winv_of(s);
            float4 x = g_h1[s * VEC_PER_ROW + c];
            x.x *= w; x.y *= w; x.z *= w; x.w *= w;
            red_add_v4(&g_h2[rep][r * VEC_PER_ROW + c], x);
        }
        for (int u = g; u < N_VIRT; u += GSTRIDE)
            g_wv[u] = winv_of(u + N_REAL);
    }

    grid_barrier();

    // ---------------- Phase 4: bcast + restore g_z invariant ----------------
    for (int t = g; t < N_VIRT * VEC_PER_ROW; t += GSTRIDE) {
        int u = t >> 4;
        int c = t & 15;
        int r = vm_idx[u] - N_REAL;
        int idx = r * VEC_PER_ROW + c;
        float4 acc = make_float4(0.f, 0.f, 0.f, 0.f);
#pragma unroll
        for (int k = 0; k < N_REP; k++) {
            float4 x = g_h2[k][idx];
            acc.x += x.x; acc.y += x.y; acc.z += x.z; acc.w += x.w;
        }
        float w = g_wv[r];
        acc.x *= w; acc.y *= w; acc.z *= w; acc.w *= w;
#pragma unroll
        for (int h = 0; h < NUM_HEADS; h++) {
            out[((size_t)u * NUM_HEADS + h) * VEC_PER_ROW + c] = acc;
        }
    }
    for (unsigned ch = g; ch < ZERO_CHUNKS; ch += GSTRIDE)
        ((float4*)&g_z)[ch] = make_float4(0.f, 0.f, 0.f, 0.f);
}

// ---------------------------------------------------------------------------
extern "C" void kernel_launch(void* const* d_in, const int* in_sizes, int n_in,
                              void* d_out, int out_size) {
    const float4* features   = (const float4*)d_in[0];  // [100000,64] f32
    const float4* virtue_emb = (const float4*)d_in[1];  // [2000,64]   f32
    const int*    cnodes     = (const int*)d_in[2];     // [30000] i32
    const int*    src        = (const int*)d_in[3];     // [512000] i32
    const int*    dst        = (const int*)d_in[4];     // [512000] i32
    const int*    vm_idx     = (const int*)d_in[5];     // [2000] i32
    float4*       out        = (float4*)d_out;          // [2000,8,64] f32

    k_all<<<NBLK, TB>>>(features, virtue_emb, cnodes, src, dst, vm_idx, out);
}

// round 17
// speedup vs baseline: 1.1088x; 1.1088x over previous
#include <cuda_runtime.h>
#include <cuda_fp16.h>
#include <cstdint>

#define NUM_HEADS   8
#define HIDDEN_DIM  64
#define N_REAL      30000
#define N_VIRT      2000
#define N_NODES     (N_REAL + N_VIRT)
#define N_EDGES     512000
#define VEC_PER_ROW 16                 // float4 (or uint2-of-half4) per node row
#define TB 256
#define BLK_PER_SM 8                   // forced by __launch_bounds__
#define NBLK (148 * BLK_PER_SM)        // 1184 — one fully co-resident wave
#define GSTRIDE (NBLK * TB)
#define N_REP 4                        // h2 replicas to de-contend REDG
#define E_PER 4

// ---- device scratch (allocation-free) --------------------------------------
// Invariant: g_z is ZERO on entry (static zero-init at load; re-zeroed in
// phase 4 on every call).
struct __align__(16) Zeroed {
    int indeg[N_NODES];
    int vcnt;
    unsigned char needed[N_NODES];
};
__device__ Zeroed  g_z;
#define ZERO_CHUNKS  ((unsigned)((sizeof(Zeroed) + 15) / 16))

__device__ __half2 g_h0h[N_NODES * 32];            // f16 node features, 4 MB
__device__ float4  g_h1[N_NODES * VEC_PER_ROW];    // round-1 raw sums, 8 MB
__device__ float4  g_h2[N_REP][N_VIRT * VEC_PER_ROW]; // round-2 replicas, 2 MB
__device__ int     g_vpack[N_EDGES];               // packed (src | vdst<<16)
__device__ float   g_wv[N_VIRT];                   // winv of virtual nodes

// software global barrier state (monotonic generation; count resets itself)
__device__ unsigned g_bar_count;
__device__ unsigned g_bar_gen;

__device__ __forceinline__ void red_add_v4(float4* addr, float4 v) {
    asm volatile("red.global.add.v4.f32 [%0], {%1,%2,%3,%4};"
                 :: "l"(addr), "f"(v.x), "f"(v.y), "f"(v.z), "f"(v.w)
                 : "memory");
}
__device__ __forceinline__ float winv_of(int node) {
    float di = (float)g_z.indeg[node];
    return di > 0.f ? __frcp_rn(di) : 0.f;
}

// Grid-wide barrier for exactly NBLK co-resident blocks.
__device__ __forceinline__ void grid_barrier() {
    __syncthreads();
    if (threadIdx.x == 0) {
        unsigned gen = *(volatile unsigned*)&g_bar_gen;
        __threadfence();                       // make phase writes visible
        unsigned arrived = atomicAdd(&g_bar_count, 1u);
        if (arrived == NBLK - 1) {
            g_bar_count = 0;
            __threadfence();
            atomicExch(&g_bar_gen, gen + 1u);  // release
        } else {
            while (*(volatile unsigned*)&g_bar_gen == gen) { __nanosleep(64); }
        }
        __threadfence();                       // acquire
    }
    __syncthreads();
}

// ---------------------------------------------------------------------------
// One persistent kernel; phases separated by grid barriers.
// __launch_bounds__(TB, BLK_PER_SM) caps regs at 32 so all NBLK blocks are
// co-resident (32 regs * 2048 threads = full RF), making the barrier safe.
__global__ void __launch_bounds__(TB, BLK_PER_SM) k_all(
        const float4* __restrict__ features,
        const float4* __restrict__ virtue_emb,
        const int* __restrict__ cnodes,
        const int* __restrict__ src,
        const int* __restrict__ dst,
        const int* __restrict__ vm_idx,
        float4* __restrict__ out) {
    const int g = blockIdx.x * TB + threadIdx.x;

    // ---------------- Phase 1: prep -----------------------------------------
    // indeg histogram + virtual-pair compaction (one pass over edges)
    for (int e = g; e < N_EDGES; e += GSTRIDE) {
        int dd = dst[e];
        atomicAdd(&g_z.indeg[dd], 1);
        if (dd >= N_REAL) {
            int s = src[e];
            int pos = atomicAdd(&g_z.vcnt, 1);
            g_vpack[pos] = s | ((dd - N_REAL) << 16);
            g_z.needed[s] = 1;                 // benign race
        }
    }
    // build f16 h0
    for (int t = g; t < N_NODES * VEC_PER_ROW; t += GSTRIDE) {
        int v = t >> 4;
        int c = t & 15;
        float4 x;
        if (v < N_REAL) {
            int w = cnodes[v];
            x = features[(size_t)w * VEC_PER_ROW + c];
        } else {
            x = virtue_emb[(size_t)(v - N_REAL) * VEC_PER_ROW + c];
        }
        g_h0h[t * 2]     = __floats2half2_rn(x.x, x.y);
        g_h0h[t * 2 + 1] = __floats2half2_rn(x.z, x.w);
    }
    // zero h1 and h2
    for (int t = g; t < N_NODES * VEC_PER_ROW; t += GSTRIDE)
        g_h1[t] = make_float4(0.f, 0.f, 0.f, 0.f);
    for (int t = g; t < N_REP * N_VIRT * VEC_PER_ROW; t += GSTRIDE)
        ((float4*)g_h2)[t] = make_float4(0.f, 0.f, 0.f, 0.f);

    grid_barrier();

    // ---------------- Phase 2: round 1 --------------------------------------
    // h1raw[d] += h0f16[s] for needed dst; 16 lanes/edge, 4 edges per item.
    {
        const uint2* h0 = reinterpret_cast<const uint2*>(g_h0h);
        const int total = (N_EDGES / E_PER) * VEC_PER_ROW;
        for (int t = g; t < total; t += GSTRIDE) {
            int c  = t & 15;
            int e0 = (t >> 4) * E_PER;

            int s[E_PER], d[E_PER];
#pragma unroll
            for (int j = 0; j < E_PER; j++) { s[j] = src[e0 + j]; d[j] = dst[e0 + j]; }
            unsigned char f[E_PER];
#pragma unroll
            for (int j = 0; j < E_PER; j++) f[j] = g_z.needed[d[j]];

            uint2 q[E_PER];
#pragma unroll
            for (int j = 0; j < E_PER; j++)
                if (f[j]) q[j] = h0[s[j] * VEC_PER_ROW + c];
#pragma unroll
            for (int j = 0; j < E_PER; j++) {
                if (!f[j]) continue;
                __half2 a  = *reinterpret_cast<__half2*>(&q[j].x);
                __half2 bb = *reinterpret_cast<__half2*>(&q[j].y);
                float2 fa = __half22float2(a);
                float2 fb = __half22float2(bb);
                red_add_v4(&g_h1[d[j] * VEC_PER_ROW + c],
                           make_float4(fa.x, fa.y, fb.x, fb.y));
            }
        }
    }

    grid_barrier();

    // ---------------- Phase 3: round 2 + g_wv -------------------------------
    {
        int nv = g_z.vcnt;
        int total = nv * VEC_PER_ROW;
        int rep = (threadIdx.x >> 5) & (N_REP - 1);
        for (int t = g; t < total; t += GSTRIDE) {
            int e = t >> 4;
            int c = t & 15;
            int pk = g_vpack[e];
            int s = pk & 0xFFFF;
            int r = pk >> 16;
            float w = winv_of(s);
            float4 x = g_h1[s * VEC_PER_ROW + c];
            x.x *= w; x.y *= w; x.z *= w; x.w *= w;
            red_add_v4(&g_h2[rep][r * VEC_PER_ROW + c], x);
        }
        for (int u = g; u < N_VIRT; u += GSTRIDE)
            g_wv[u] = winv_of(u + N_REAL);
    }

    grid_barrier();

    // ---------------- Phase 4: bcast + restore g_z invariant ----------------
    for (int t = g; t < N_VIRT * VEC_PER_ROW; t += GSTRIDE) {
        int u = t >> 4;
        int c = t & 15;
        int r = vm_idx[u] - N_REAL;
        int idx = r * VEC_PER_ROW + c;
        float4 acc = make_float4(0.f, 0.f, 0.f, 0.f);
#pragma unroll
        for (int k = 0; k < N_REP; k++) {
            float4 x = g_h2[k][idx];
            acc.x += x.x; acc.y += x.y; acc.z += x.z; acc.w += x.w;
        }
        float w = g_wv[r];
        acc.x *= w; acc.y *= w; acc.z *= w; acc.w *= w;
#pragma unroll
        for (int h = 0; h < NUM_HEADS; h++) {
            out[((size_t)u * NUM_HEADS + h) * VEC_PER_ROW + c] = acc;
        }
    }
    for (unsigned ch = g; ch < ZERO_CHUNKS; ch += GSTRIDE)
        ((float4*)&g_z)[ch] = make_float4(0.f, 0.f, 0.f, 0.f);
}

// ---------------------------------------------------------------------------
extern "C" void kernel_launch(void* const* d_in, const int* in_sizes, int n_in,
                              void* d_out, int out_size) {
    const float4* features   = (const float4*)d_in[0];  // [100000,64] f32
    const float4* virtue_emb = (const float4*)d_in[1];  // [2000,64]   f32
    const int*    cnodes     = (const int*)d_in[2];     // [30000] i32
    const int*    src        = (const int*)d_in[3];     // [512000] i32
    const int*    dst        = (const int*)d_in[4];     // [512000] i32
    const int*    vm_idx     = (const int*)d_in[5];     // [2000] i32
    float4*       out        = (float4*)d_out;          // [2000,8,64] f32

    k_all<<<NBLK, TB>>>(features, virtue_emb, cnodes, src, dst, vm_idx, out);
}